// round 11
// baseline (speedup 1.0000x reference)
#include <cuda_runtime.h>
#include <cuda_bf16.h>
#include <cstdint>

// Problem constants
#define Z   16
#define Y   384
#define X   384
#define SL  (Y*X)            // 147456 voxels per slice
#define CX  385              // cells per axis
#define NTX 13               // ceil(385/32)  (tile 32 cells in x)
#define NTY 25               // ceil(385/16)  (tile 16 cells in y, 2 per thread)
#define FR  17               // footprint rows per slice
#define FC  33               // footprint cols per slice
#define FPN (FR*FC)          // 561
#define SSTR 36              // smem row stride (words)
#define EPSF 1e-12f

// Zero at load; reset by the last block each launch (graph-replay invariant).
__device__ double g_acc[3];
__device__ unsigned g_ticket;

// Pack one voxel: bit31 = label, bit0 = (p>0) i.e. s>0.5, magnitude = |s - l|.
__device__ __forceinline__ unsigned packv(float p, int l) {
    unsigned lbit = (unsigned)l << 31;
    float t = __uint_as_float(__float_as_uint(p) ^ lbit);   // l ? -p : p
    float aw = __fdividef(1.0f, 1.0f + __expf(-t));         // |s - l| = sigmoid(t)
    unsigned pb = (p > 0.0f) ? 1u : 0u;
    return (__float_as_uint(aw) & 0x7FFFFFFEu) | lbit | pb;
}

__device__ __forceinline__ float bterm(unsigned u) {
    float aw = __uint_as_float(u & 0x7FFFFFFFu);            // |w| (LSB noise ~2^-24)
    return __logf(fmaxf(1.0f - aw, EPSF));
}

__global__ void __launch_bounds__(256) k_fused(const float* __restrict__ pred,
                                               const int*   __restrict__ lab,
                                               const float* __restrict__ area,
                                               float*       __restrict__ out) {
    __shared__ unsigned sS[FR][SSTR];   // one packed slice
    __shared__ float sA[256];
    __shared__ float rN[8], rD[8], rB[8];

    const int tid = threadIdx.x;
    sA[tid] = area[tid];

    const int lx = tid & 31, ly = tid >> 5;
    const int vx0 = blockIdx.x * 32;
    const int vy0 = blockIdx.y * 16;
    const int cx = vx0 + lx;
    const int cy0 = vy0 + 2 * ly;
    const bool valid0 = (cx < CX) && (cy0 < CX);
    const bool valid1 = (cx < CX) && (cy0 + 1 < CX);

    // Footprint items (fixed per thread): tid, tid+256, tid+512 (<561).
    int  gi[3], so[3];
    bool gv[3];
    const bool has2 = (tid + 512) < FPN;
#pragma unroll
    for (int k = 0; k < 3; k++) {
        int it = tid + k * 256;
        bool has = (k < 2) || has2;
        int r = it / FC, c = it - r * FC;
        int vy = vy0 + r, vx = vx0 + c;
        gv[k] = has && (vy >= 1) && (vy <= Y) && (vx >= 1) && (vx <= X);
        gi[k] = gv[k] ? ((vy - 1) * X + (vx - 1)) : 0;
        so[k] = has ? (r * SSTR + c) : 0;
    }
    unsigned* sFlat = &sS[0][0];

    // Prologue: pack padded slice 1 (real slice 0).
    unsigned pk0 = 0, pk1 = 0, pk2 = 0;
    if (gv[0]) pk0 = packv(__ldg(pred + gi[0]), __ldg(lab + gi[0]));
    if (gv[1]) pk1 = packv(__ldg(pred + gi[1]), __ldg(lab + gi[1]));
    if (gv[2]) pk2 = packv(__ldg(pred + gi[2]), __ldg(lab + gi[2]));

    float accN = 0.0f, accD = 0.0f, accB = 0.0f;

    // Prev-slice carry (padded slice 0 = zeros).
    unsigned pL0 = 0, pP0 = 0, pL1 = 0, pP1 = 0;
    float psq0 = 0.0f, psq1 = 0.0f;
    unsigned pu0 = 0, pu1 = 0, pu2 = 0, pu3 = 0, pu4 = 0, pu5 = 0;

    for (int zp = 0; zp <= Z; zp++) {
        sFlat[so[0]] = pk0;
        sFlat[so[1]] = pk1;
        if (has2) sFlat[so[2]] = pk2;
        __syncthreads();

        // Prefetch padded slice zp+2 (real iff zp <= 14).
        float rp0 = 0.0f, rp1 = 0.0f, rp2 = 0.0f;
        int   rl0 = 0,    rl1 = 0,    rl2 = 0;
        const bool pf = (zp <= Z - 2);
        if (pf) {
            const int base = (zp + 1) * SL;
            if (gv[0]) { rp0 = __ldg(pred + base + gi[0]); rl0 = __ldg(lab + base + gi[0]); }
            if (gv[1]) { rp1 = __ldg(pred + base + gi[1]); rl1 = __ldg(lab + base + gi[1]); }
            if (gv[2]) { rp2 = __ldg(pred + base + gi[2]); rl2 = __ldg(lab + base + gi[2]); }
        }

        // Compute 2 vertically adjacent cells (rows 2ly, 2ly+1).
        unsigned u0 = sS[2 * ly][lx],     u1 = sS[2 * ly][lx + 1];
        unsigned u2 = sS[2 * ly + 1][lx], u3 = sS[2 * ly + 1][lx + 1];
        unsigned u4 = sS[2 * ly + 2][lx], u5 = sS[2 * ly + 2][lx + 1];

        unsigned cL0 = (u0 >> 31) | ((u1 >> 31) << 1) | ((u2 >> 31) << 2) | ((u3 >> 31) << 3);
        unsigned cP0 = (u0 & 1u)  | ((u1 & 1u) << 1)  | ((u2 & 1u) << 2)  | ((u3 & 1u) << 3);
        unsigned cL1 = (u2 >> 31) | ((u3 >> 31) << 1) | ((u4 >> 31) << 2) | ((u5 >> 31) << 3);
        unsigned cP1 = (u2 & 1u)  | ((u3 & 1u) << 1)  | ((u4 & 1u) << 2)  | ((u5 & 1u) << 3);

        float w0 = __uint_as_float(u0), w1 = __uint_as_float(u1);
        float w2 = __uint_as_float(u2), w3 = __uint_as_float(u3);
        float w4 = __uint_as_float(u4), w5 = __uint_as_float(u5);
        float s01 = fmaf(w0, w0, w1 * w1);
        float s23 = fmaf(w2, w2, w3 * w3);
        float s45 = fmaf(w4, w4, w5 * w5);
        float sq0 = s01 + s23;
        float sq1 = s23 + s45;

        int code0  = (int)(pL0 | (cL0 << 4));
        int pcode0 = (int)(pP0 | (cP0 << 4));
        int code1  = (int)(pL1 | (cL1 << 4));
        int pcode1 = (int)(pP1 | (cP1 << 4));

        if (valid0) {
            float d2 = psq0 + sq0;
            float la = sA[code0], pa = sA[pcode0];
            accN = fmaf(fmaf(d2, -0.125f, 1.0f), la, accN);
            accD += la + pa;
            if (code0 == 0 || code0 == 255) {
                accB -= bterm(pu0) + bterm(pu1) + bterm(pu2) + bterm(pu3)
                      + bterm(u0)  + bterm(u1)  + bterm(u2)  + bterm(u3);
            }
        }
        if (valid1) {
            float d2 = psq1 + sq1;
            float la = sA[code1], pa = sA[pcode1];
            accN = fmaf(fmaf(d2, -0.125f, 1.0f), la, accN);
            accD += la + pa;
            if (code1 == 0 || code1 == 255) {
                accB -= bterm(pu2) + bterm(pu3) + bterm(pu4) + bterm(pu5)
                      + bterm(u2)  + bterm(u3)  + bterm(u4)  + bterm(u5);
            }
        }

        pL0 = cL0; pP0 = cP0; pL1 = cL1; pP1 = cP1;
        psq0 = sq0; psq1 = sq1;
        pu0 = u0; pu1 = u1; pu2 = u2; pu3 = u3; pu4 = u4; pu5 = u5;

        // Pack prefetched slice (LDG latency hidden behind compute).
        pk0 = (pf && gv[0]) ? packv(rp0, rl0) : 0u;
        pk1 = (pf && gv[1]) ? packv(rp1, rl1) : 0u;
        pk2 = (pf && gv[2]) ? packv(rp2, rl2) : 0u;

        __syncthreads();
    }

    // Block reduction -> double atomics -> last-block finalize.
#pragma unroll
    for (int o = 16; o > 0; o >>= 1) {
        accN += __shfl_down_sync(0xffffffffu, accN, o);
        accD += __shfl_down_sync(0xffffffffu, accD, o);
        accB += __shfl_down_sync(0xffffffffu, accB, o);
    }
    int wid = tid >> 5, lane = tid & 31;
    if (lane == 0) { rN[wid] = accN; rD[wid] = accD; rB[wid] = accB; }
    __syncthreads();
    if (tid == 0) {
        float n = 0.0f, d = 0.0f, b = 0.0f;
#pragma unroll
        for (int i = 0; i < 8; i++) { n += rN[i]; d += rD[i]; b += rB[i]; }
        atomicAdd(&g_acc[0], (double)n);
        atomicAdd(&g_acc[1], (double)d);
        atomicAdd(&g_acc[2], (double)b);
        __threadfence();
        unsigned tk = atomicAdd(&g_ticket, 1u);
        if (tk == (unsigned)(NTX * NTY - 1)) {
            __threadfence();
            double num = 2.0 * g_acc[0];
            double den = g_acc[1];
            double vol = g_acc[2] / (8.0 * (double)CX * (double)CX);
            double dice = 1.0 - (num + 1e-3) / (den + 1e-3);
            out[0] = (float)(dice + vol);
            g_acc[0] = 0.0; g_acc[1] = 0.0; g_acc[2] = 0.0;
            g_ticket = 0u;
            __threadfence();
        }
    }
}

extern "C" void kernel_launch(void* const* d_in, const int* in_sizes, int n_in,
                              void* d_out, int out_size) {
    const float* pred = (const float*)d_in[0];
    const int*   lab  = (const int*)d_in[1];
    const float* area = (const float*)d_in[2];
    (void)in_sizes; (void)n_in; (void)out_size;

    dim3 grid(NTX, NTY);
    k_fused<<<grid, 256>>>(pred, lab, area, (float*)d_out);
}

// round 13
// speedup vs baseline: 1.6833x; 1.6833x over previous
#include <cuda_runtime.h>
#include <cuda_bf16.h>
#include <cstdint>

// Problem constants
#define Z   16
#define Y   384
#define X   384
#define SL  (Y*X)            // 147456 voxels per slice
#define CX  385              // cells per axis
#define NTX 13               // ceil(385/32)  (tile 32 cells in x)
#define NTY 25               // ceil(385/16)  (tile 16 cells in y, 2 per thread)
#define NCHUNK 4             // z-pair chunks per tile
#define FR  17               // footprint rows per slice
#define FC  33               // footprint cols per slice
#define FPN (FR*FC)          // 561
#define SSTR 36              // smem row stride (words)
#define EPSF 1e-12f

// Zero at load; reset by the last block each launch (graph-replay invariant).
__device__ double g_acc[3];
__device__ unsigned g_ticket;

// Pack one voxel: bit31 = label, bit0 = (p>0) i.e. s>0.5, magnitude = |s - l|.
__device__ __forceinline__ unsigned packv(float p, int l) {
    unsigned lbit = (unsigned)l << 31;
    float t = __uint_as_float(__float_as_uint(p) ^ lbit);   // l ? -p : p
    float aw = __fdividef(1.0f, 1.0f + __expf(-t));         // |s - l| = sigmoid(t)
    unsigned pb = (p > 0.0f) ? 1u : 0u;
    return (__float_as_uint(aw) & 0x7FFFFFFEu) | lbit | pb;
}

__device__ __forceinline__ float bterm(unsigned u) {
    float aw = __uint_as_float(u & 0x7FFFFFFFu);            // |w| (LSB noise ~2^-24)
    return __logf(fmaxf(1.0f - aw, EPSF));
}

__global__ void __launch_bounds__(256) k_fused(const float* __restrict__ pred,
                                               const int*   __restrict__ lab,
                                               const float* __restrict__ area,
                                               float*       __restrict__ out) {
    __shared__ unsigned sS[FR][SSTR];   // one packed slice
    __shared__ float sA[256];
    __shared__ float rN[8], rD[8], rB[8];

    const int tid = threadIdx.x;
    sA[tid] = area[tid];

    const int lx = tid & 31, ly = tid >> 5;
    const int vx0 = blockIdx.x * 32;
    const int vy0 = blockIdx.y * 16;
    const int cx = vx0 + lx;
    const int cy0 = vy0 + 2 * ly;
    const bool valid0 = (cx < CX) && (cy0 < CX);
    const bool valid1 = (cx < CX) && (cy0 + 1 < CX);

    // z-pair chunk: starts {0,5,9,13}, lens {5,4,4,4}
    const int bz = blockIdx.z;
    const int z0 = bz * 4 + (bz > 0 ? 1 : 0);
    const int zend = z0 + (bz == 0 ? 5 : 4);    // exclusive

    // Footprint items (fixed per thread): tid, tid+256, tid+512 (<561).
    int  gi[3], so[3];
    bool gv[3];
    const bool has2 = (tid + 512) < FPN;
#pragma unroll
    for (int k = 0; k < 3; k++) {
        int it = tid + k * 256;
        bool has = (k < 2) || has2;
        int r = it / FC, c = it - r * FC;
        int vy = vy0 + r, vx = vx0 + c;
        gv[k] = has && (vy >= 1) && (vy <= Y) && (vx >= 1) && (vx <= X);
        gi[k] = gv[k] ? ((vy - 1) * X + (vx - 1)) : 0;
        so[k] = has ? (r * SSTR + c) : 0;
    }
    unsigned* sFlat = &sS[0][0];

    // ---- Carry init: padded slice z0 (real slice z0-1; zeros if z0==0) ----
    unsigned pk0 = 0, pk1 = 0, pk2 = 0;
    if (z0 >= 1) {
        const int base = (z0 - 1) * SL;
        if (gv[0]) pk0 = packv(__ldg(pred + base + gi[0]), __ldg(lab + base + gi[0]));
        if (gv[1]) pk1 = packv(__ldg(pred + base + gi[1]), __ldg(lab + base + gi[1]));
        if (gv[2]) pk2 = packv(__ldg(pred + base + gi[2]), __ldg(lab + base + gi[2]));
    }
    sFlat[so[0]] = pk0;
    sFlat[so[1]] = pk1;
    if (has2) sFlat[so[2]] = pk2;
    __syncthreads();

    unsigned pu0 = sS[2 * ly][lx],     pu1 = sS[2 * ly][lx + 1];
    unsigned pu2 = sS[2 * ly + 1][lx], pu3 = sS[2 * ly + 1][lx + 1];
    unsigned pu4 = sS[2 * ly + 2][lx], pu5 = sS[2 * ly + 2][lx + 1];

    unsigned pL0 = (pu0 >> 31) | ((pu1 >> 31) << 1) | ((pu2 >> 31) << 2) | ((pu3 >> 31) << 3);
    unsigned pP0 = (pu0 & 1u)  | ((pu1 & 1u) << 1)  | ((pu2 & 1u) << 2)  | ((pu3 & 1u) << 3);
    unsigned pL1 = (pu2 >> 31) | ((pu3 >> 31) << 1) | ((pu4 >> 31) << 2) | ((pu5 >> 31) << 3);
    unsigned pP1 = (pu2 & 1u)  | ((pu3 & 1u) << 1)  | ((pu4 & 1u) << 2)  | ((pu5 & 1u) << 3);
    {
        float w0 = __uint_as_float(pu0), w1 = __uint_as_float(pu1);
        float w2 = __uint_as_float(pu2), w3 = __uint_as_float(pu3);
        float w4 = __uint_as_float(pu4), w5 = __uint_as_float(pu5);
        float s01 = fmaf(w0, w0, w1 * w1);
        float s23 = fmaf(w2, w2, w3 * w3);
        float s45 = fmaf(w4, w4, w5 * w5);
        pu0 = __float_as_uint(s01 + s23);   // reuse pu0? no -- keep separate
        pu0 = sS[2 * ly][lx];               // restore (cheap reload)
        // carried square sums:
        (void)0;
        // store in dedicated regs below
    }
    float psq0, psq1;
    {
        float w0 = __uint_as_float(pu0 & 0x7FFFFFFFu), w1 = __uint_as_float(pu1 & 0x7FFFFFFFu);
        float w2 = __uint_as_float(pu2 & 0x7FFFFFFFu), w3 = __uint_as_float(pu3 & 0x7FFFFFFFu);
        float w4 = __uint_as_float(pu4 & 0x7FFFFFFFu), w5 = __uint_as_float(pu5 & 0x7FFFFFFFu);
        float s01 = fmaf(w0, w0, w1 * w1);
        float s23 = fmaf(w2, w2, w3 * w3);
        float s45 = fmaf(w4, w4, w5 * w5);
        psq0 = s01 + s23;
        psq1 = s23 + s45;
    }

    // Pack padded slice z0+1 (real slice z0; always real since z0 <= 13).
    {
        const int base = z0 * SL;
        pk0 = gv[0] ? packv(__ldg(pred + base + gi[0]), __ldg(lab + base + gi[0])) : 0u;
        pk1 = gv[1] ? packv(__ldg(pred + base + gi[1]), __ldg(lab + base + gi[1])) : 0u;
        pk2 = gv[2] ? packv(__ldg(pred + base + gi[2]), __ldg(lab + base + gi[2])) : 0u;
    }
    __syncthreads();

    float accN = 0.0f, accD = 0.0f, accB = 0.0f;

    for (int zp = z0; zp < zend; zp++) {
        sFlat[so[0]] = pk0;
        sFlat[so[1]] = pk1;
        if (has2) sFlat[so[2]] = pk2;
        __syncthreads();

        // Prefetch padded slice zp+2 (needed iff another iteration follows;
        // real iff zp+2 <= Z).
        float rp0 = 0.0f, rp1 = 0.0f, rp2 = 0.0f;
        int   rl0 = 0,    rl1 = 0,    rl2 = 0;
        const bool pf = (zp < zend - 1) && (zp + 2 <= Z);
        if (pf) {
            const int base = (zp + 1) * SL;
            if (gv[0]) { rp0 = __ldg(pred + base + gi[0]); rl0 = __ldg(lab + base + gi[0]); }
            if (gv[1]) { rp1 = __ldg(pred + base + gi[1]); rl1 = __ldg(lab + base + gi[1]); }
            if (gv[2]) { rp2 = __ldg(pred + base + gi[2]); rl2 = __ldg(lab + base + gi[2]); }
        }

        // Compute 2 vertically adjacent cells (rows 2ly, 2ly+1).
        unsigned u0 = sS[2 * ly][lx],     u1 = sS[2 * ly][lx + 1];
        unsigned u2 = sS[2 * ly + 1][lx], u3 = sS[2 * ly + 1][lx + 1];
        unsigned u4 = sS[2 * ly + 2][lx], u5 = sS[2 * ly + 2][lx + 1];

        unsigned cL0 = (u0 >> 31) | ((u1 >> 31) << 1) | ((u2 >> 31) << 2) | ((u3 >> 31) << 3);
        unsigned cP0 = (u0 & 1u)  | ((u1 & 1u) << 1)  | ((u2 & 1u) << 2)  | ((u3 & 1u) << 3);
        unsigned cL1 = (u2 >> 31) | ((u3 >> 31) << 1) | ((u4 >> 31) << 2) | ((u5 >> 31) << 3);
        unsigned cP1 = (u2 & 1u)  | ((u3 & 1u) << 1)  | ((u4 & 1u) << 2)  | ((u5 & 1u) << 3);

        float w0 = __uint_as_float(u0), w1 = __uint_as_float(u1);
        float w2 = __uint_as_float(u2), w3 = __uint_as_float(u3);
        float w4 = __uint_as_float(u4), w5 = __uint_as_float(u5);
        float s01 = fmaf(w0, w0, w1 * w1);
        float s23 = fmaf(w2, w2, w3 * w3);
        float s45 = fmaf(w4, w4, w5 * w5);
        float sq0 = s01 + s23;
        float sq1 = s23 + s45;

        int code0  = (int)(pL0 | (cL0 << 4));
        int pcode0 = (int)(pP0 | (cP0 << 4));
        int code1  = (int)(pL1 | (cL1 << 4));
        int pcode1 = (int)(pP1 | (cP1 << 4));

        if (valid0) {
            float d2 = psq0 + sq0;
            float la = sA[code0], pa = sA[pcode0];
            accN = fmaf(fmaf(d2, -0.125f, 1.0f), la, accN);
            accD += la + pa;
            if (code0 == 0 || code0 == 255) {
                accB -= bterm(pu0) + bterm(pu1) + bterm(pu2) + bterm(pu3)
                      + bterm(u0)  + bterm(u1)  + bterm(u2)  + bterm(u3);
            }
        }
        if (valid1) {
            float d2 = psq1 + sq1;
            float la = sA[code1], pa = sA[pcode1];
            accN = fmaf(fmaf(d2, -0.125f, 1.0f), la, accN);
            accD += la + pa;
            if (code1 == 0 || code1 == 255) {
                accB -= bterm(pu2) + bterm(pu3) + bterm(pu4) + bterm(pu5)
                      + bterm(u2)  + bterm(u3)  + bterm(u4)  + bterm(u5);
            }
        }

        pL0 = cL0; pP0 = cP0; pL1 = cL1; pP1 = cP1;
        psq0 = sq0; psq1 = sq1;
        pu0 = u0; pu1 = u1; pu2 = u2; pu3 = u3; pu4 = u4; pu5 = u5;

        // Pack prefetched slice (LDG latency hidden behind compute).
        pk0 = (pf && gv[0]) ? packv(rp0, rl0) : 0u;
        pk1 = (pf && gv[1]) ? packv(rp1, rl1) : 0u;
        pk2 = (pf && gv[2]) ? packv(rp2, rl2) : 0u;

        __syncthreads();
    }

    // Block reduction -> double atomics -> last-block finalize.
#pragma unroll
    for (int o = 16; o > 0; o >>= 1) {
        accN += __shfl_down_sync(0xffffffffu, accN, o);
        accD += __shfl_down_sync(0xffffffffu, accD, o);
        accB += __shfl_down_sync(0xffffffffu, accB, o);
    }
    int wid = tid >> 5, lane = tid & 31;
    if (lane == 0) { rN[wid] = accN; rD[wid] = accD; rB[wid] = accB; }
    __syncthreads();
    if (tid == 0) {
        float n = 0.0f, d = 0.0f, b = 0.0f;
#pragma unroll
        for (int i = 0; i < 8; i++) { n += rN[i]; d += rD[i]; b += rB[i]; }
        atomicAdd(&g_acc[0], (double)n);
        atomicAdd(&g_acc[1], (double)d);
        atomicAdd(&g_acc[2], (double)b);
        __threadfence();
        unsigned tk = atomicAdd(&g_ticket, 1u);
        if (tk == (unsigned)(NTX * NTY * NCHUNK - 1)) {
            __threadfence();
            double num = 2.0 * g_acc[0];
            double den = g_acc[1];
            double vol = g_acc[2] / (8.0 * (double)CX * (double)CX);
            double dice = 1.0 - (num + 1e-3) / (den + 1e-3);
            out[0] = (float)(dice + vol);
            g_acc[0] = 0.0; g_acc[1] = 0.0; g_acc[2] = 0.0;
            g_ticket = 0u;
            __threadfence();
        }
    }
}

extern "C" void kernel_launch(void* const* d_in, const int* in_sizes, int n_in,
                              void* d_out, int out_size) {
    const float* pred = (const float*)d_in[0];
    const int*   lab  = (const int*)d_in[1];
    const float* area = (const float*)d_in[2];
    (void)in_sizes; (void)n_in; (void)out_size;

    dim3 grid(NTX, NTY, NCHUNK);
    k_fused<<<grid, 256>>>(pred, lab, area, (float*)d_out);
}

// round 14
// speedup vs baseline: 1.7620x; 1.0468x over previous
#include <cuda_runtime.h>
#include <cuda_bf16.h>
#include <cstdint>

// Problem constants
#define Z   16
#define Y   384
#define X   384
#define SL  (Y*X)            // 147456 voxels per slice
#define CX  385              // cells per axis
#define NTX 13               // ceil(385/32)
#define NTY 25               // ceil(385/16), 2 cells/thread in y
#define NCHUNK 4             // z-pair chunks per tile
#define FR  17               // footprint rows per slice
#define FC  33               // footprint cols per slice
#define FPN (FR*FC)          // 561
#define SSTR 36              // smem row stride (words)
#define EPSF 1e-12f

// Zero at load; reset by the last block each launch (graph-replay invariant).
__device__ double g_acc[3];
__device__ unsigned g_ticket;

// Pack one voxel: bit31 = label, bit0 = (p>0) i.e. s>0.5, magnitude = |s - l|.
__device__ __forceinline__ unsigned packv(float p, int l) {
    unsigned lbit = (unsigned)l << 31;
    float t = __uint_as_float(__float_as_uint(p) ^ lbit);   // l ? -p : p
    float aw = __fdividef(1.0f, 1.0f + __expf(-t));         // |s - l| = sigmoid(t)
    unsigned pb = (p > 0.0f) ? 1u : 0u;
    return (__float_as_uint(aw) & 0x7FFFFFFEu) | lbit | pb;
}

__global__ void __launch_bounds__(256) k_fused(const float* __restrict__ pred,
                                               const int*   __restrict__ lab,
                                               const float* __restrict__ area,
                                               float*       __restrict__ out) {
    __shared__ unsigned sS[2][FR][SSTR];   // double-buffered packed slices
    __shared__ float sA[256];
    __shared__ float rN[8], rD[8], rB[8];

    const int tid = threadIdx.x;
    sA[tid] = area[tid];

    const int lx = tid & 31, ly = tid >> 5;
    const int ry = 2 * ly;
    const int vx0 = blockIdx.x * 32;
    const int vy0 = blockIdx.y * 16;
    const bool valid0 = (vx0 + lx < CX) && (vy0 + ry < CX);
    const bool valid1 = (vx0 + lx < CX) && (vy0 + ry + 1 < CX);

    // z-pair chunk: starts {0,5,9,13}, lens {5,4,4,4}
    const int bz = blockIdx.z;
    const int z0 = bz * 4 + (bz > 0 ? 1 : 0);
    const int zend = z0 + (bz == 0 ? 5 : 4);    // exclusive

    // Footprint items (fixed per thread): tid, tid+256, tid+512 (<561).
    int  gi[3], so[3];
    bool gv[3];
    const bool has2 = (tid + 512) < FPN;
#pragma unroll
    for (int k = 0; k < 3; k++) {
        int it = tid + k * 256;
        bool has = (k < 2) || has2;
        int r = it / FC, c = it - r * FC;
        int vy = vy0 + r, vx = vx0 + c;
        gv[k] = has && (vy >= 1) && (vy <= Y) && (vx >= 1) && (vx <= X);
        gi[k] = gv[k] ? ((vy - 1) * X + (vx - 1)) : 0;
        so[k] = has ? (r * SSTR + c) : 0;
    }

    const int eb = (z0 + 1) & 1;   // carry scratch buffer
    const int ob = z0 & 1;         // buffer read by first loop iter
    unsigned* bufE = &sS[eb][0][0];
    unsigned* bufO = &sS[ob][0][0];

    // ---- Prologue: carry slice (padded z0; zeros if z0==0) ----
    unsigned pk0 = 0, pk1 = 0, pk2 = 0;
    if (z0 >= 1) {
        const int base = (z0 - 1) * SL;
        if (gv[0]) pk0 = packv(__ldg(pred + base + gi[0]), __ldg(lab + base + gi[0]));
        if (gv[1]) pk1 = packv(__ldg(pred + base + gi[1]), __ldg(lab + base + gi[1]));
        if (gv[2]) pk2 = packv(__ldg(pred + base + gi[2]), __ldg(lab + base + gi[2]));
    }
    bufE[so[0]] = pk0; bufE[so[1]] = pk1; if (has2) bufE[so[2]] = pk2;
    __syncthreads();

    unsigned pL0, pP0, pL1, pP1;
    float psq0, psq1, pt01, pt23, pt45;
    {
        unsigned c0 = sS[eb][ry][lx],     c1 = sS[eb][ry][lx + 1];
        unsigned c2 = sS[eb][ry + 1][lx], c3 = sS[eb][ry + 1][lx + 1];
        unsigned c4 = sS[eb][ry + 2][lx], c5 = sS[eb][ry + 2][lx + 1];
        pL0 = (c0 >> 31) | ((c1 >> 31) << 1) | ((c2 >> 31) << 2) | ((c3 >> 31) << 3);
        pP0 = (c0 & 1u)  | ((c1 & 1u) << 1)  | ((c2 & 1u) << 2)  | ((c3 & 1u) << 3);
        pL1 = (c2 >> 31) | ((c3 >> 31) << 1) | ((c4 >> 31) << 2) | ((c5 >> 31) << 3);
        pP1 = (c2 & 1u)  | ((c3 & 1u) << 1)  | ((c4 & 1u) << 2)  | ((c5 & 1u) << 3);
        float a0 = __uint_as_float(c0 & 0x7FFFFFFFu), a1 = __uint_as_float(c1 & 0x7FFFFFFFu);
        float a2 = __uint_as_float(c2 & 0x7FFFFFFFu), a3 = __uint_as_float(c3 & 0x7FFFFFFFu);
        float a4 = __uint_as_float(c4 & 0x7FFFFFFFu), a5 = __uint_as_float(c5 & 0x7FFFFFFFu);
        float s01 = fmaf(a0, a0, a1 * a1);
        float s23 = fmaf(a2, a2, a3 * a3);
        float s45 = fmaf(a4, a4, a5 * a5);
        psq0 = s01 + s23;  psq1 = s23 + s45;
        pt01 = fmaxf(1.0f - a0, EPSF) * fmaxf(1.0f - a1, EPSF);
        pt23 = fmaxf(1.0f - a2, EPSF) * fmaxf(1.0f - a3, EPSF);
        pt45 = fmaxf(1.0f - a4, EPSF) * fmaxf(1.0f - a5, EPSF);
    }

    // Pack slice z0+1 (always real) -> bufO; pre-pack slice z0+2 (always real) -> pk.
    {
        const int base = z0 * SL;
        pk0 = gv[0] ? packv(__ldg(pred + base + gi[0]), __ldg(lab + base + gi[0])) : 0u;
        pk1 = gv[1] ? packv(__ldg(pred + base + gi[1]), __ldg(lab + base + gi[1])) : 0u;
        pk2 = gv[2] ? packv(__ldg(pred + base + gi[2]), __ldg(lab + base + gi[2])) : 0u;
    }
    bufO[so[0]] = pk0; bufO[so[1]] = pk1; if (has2) bufO[so[2]] = pk2;
    {
        const int base = (z0 + 1) * SL;
        pk0 = gv[0] ? packv(__ldg(pred + base + gi[0]), __ldg(lab + base + gi[0])) : 0u;
        pk1 = gv[1] ? packv(__ldg(pred + base + gi[1]), __ldg(lab + base + gi[1])) : 0u;
        pk2 = gv[2] ? packv(__ldg(pred + base + gi[2]), __ldg(lab + base + gi[2])) : 0u;
    }
    __syncthreads();

    float accN = 0.0f, accD = 0.0f, accB = 0.0f;

    // ONE sync per iteration: reads (buf rb) precede writes (buf wb); adjacent
    // iterations' conflicting accesses are separated by the trailing barrier.
    for (int zp = z0; zp < zend; zp++) {
        const int rb = zp & 1, wb = (zp + 1) & 1;

        unsigned u0 = sS[rb][ry][lx],     u1 = sS[rb][ry][lx + 1];
        unsigned u2 = sS[rb][ry + 1][lx], u3 = sS[rb][ry + 1][lx + 1];
        unsigned u4 = sS[rb][ry + 2][lx], u5 = sS[rb][ry + 2][lx + 1];

        unsigned* bW = &sS[wb][0][0];
        bW[so[0]] = pk0; bW[so[1]] = pk1; if (has2) bW[so[2]] = pk2;

        // Prefetch padded slice zp+3 (read at iter zp+2; real iff zp+3 <= Z).
        const bool pf = (zp + 2 < zend) && (zp + 3 <= Z);
        float rp0 = 0.0f, rp1 = 0.0f, rp2 = 0.0f;
        int   rl0 = 0,    rl1 = 0,    rl2 = 0;
        if (pf) {
            const int base = (zp + 2) * SL;
            if (gv[0]) { rp0 = __ldg(pred + base + gi[0]); rl0 = __ldg(lab + base + gi[0]); }
            if (gv[1]) { rp1 = __ldg(pred + base + gi[1]); rl1 = __ldg(lab + base + gi[1]); }
            if (gv[2]) { rp2 = __ldg(pred + base + gi[2]); rl2 = __ldg(lab + base + gi[2]); }
        }

        unsigned cL0 = (u0 >> 31) | ((u1 >> 31) << 1) | ((u2 >> 31) << 2) | ((u3 >> 31) << 3);
        unsigned cP0 = (u0 & 1u)  | ((u1 & 1u) << 1)  | ((u2 & 1u) << 2)  | ((u3 & 1u) << 3);
        unsigned cL1 = (u2 >> 31) | ((u3 >> 31) << 1) | ((u4 >> 31) << 2) | ((u5 >> 31) << 3);
        unsigned cP1 = (u2 & 1u)  | ((u3 & 1u) << 1)  | ((u4 & 1u) << 2)  | ((u5 & 1u) << 3);

        float a0 = __uint_as_float(u0 & 0x7FFFFFFFu), a1 = __uint_as_float(u1 & 0x7FFFFFFFu);
        float a2 = __uint_as_float(u2 & 0x7FFFFFFFu), a3 = __uint_as_float(u3 & 0x7FFFFFFFu);
        float a4 = __uint_as_float(u4 & 0x7FFFFFFFu), a5 = __uint_as_float(u5 & 0x7FFFFFFFu);
        float s01 = fmaf(a0, a0, a1 * a1);
        float s23 = fmaf(a2, a2, a3 * a3);
        float s45 = fmaf(a4, a4, a5 * a5);
        float sq0 = s01 + s23, sq1 = s23 + s45;

        float t01 = fmaxf(1.0f - a0, EPSF) * fmaxf(1.0f - a1, EPSF);
        float t23 = fmaxf(1.0f - a2, EPSF) * fmaxf(1.0f - a3, EPSF);
        float t45 = fmaxf(1.0f - a4, EPSF) * fmaxf(1.0f - a5, EPSF);

        int code0  = (int)(pL0 | (cL0 << 4));
        int pcode0 = (int)(pP0 | (cP0 << 4));
        int code1  = (int)(pL1 | (cL1 << 4));
        int pcode1 = (int)(pP1 | (cP1 << 4));

        if (valid0) {
            float d2 = psq0 + sq0;
            float la = sA[code0], pa = sA[pcode0];
            accN = fmaf(fmaf(d2, -0.125f, 1.0f), la, accN);
            accD += la + pa;
            if (code0 == 0 || code0 == 255)
                accB -= __logf((pt01 * pt23) * (t01 * t23));
        }
        if (valid1) {
            float d2 = psq1 + sq1;
            float la = sA[code1], pa = sA[pcode1];
            accN = fmaf(fmaf(d2, -0.125f, 1.0f), la, accN);
            accD += la + pa;
            if (code1 == 0 || code1 == 255)
                accB -= __logf((pt23 * pt45) * (t23 * t45));
        }

        pL0 = cL0; pP0 = cP0; pL1 = cL1; pP1 = cP1;
        psq0 = sq0; psq1 = sq1;
        pt01 = t01; pt23 = t23; pt45 = t45;

        pk0 = (pf && gv[0]) ? packv(rp0, rl0) : 0u;
        pk1 = (pf && gv[1]) ? packv(rp1, rl1) : 0u;
        pk2 = (pf && gv[2]) ? packv(rp2, rl2) : 0u;

        __syncthreads();
    }

    // Block reduction -> double atomics -> last-block finalize.
#pragma unroll
    for (int o = 16; o > 0; o >>= 1) {
        accN += __shfl_down_sync(0xffffffffu, accN, o);
        accD += __shfl_down_sync(0xffffffffu, accD, o);
        accB += __shfl_down_sync(0xffffffffu, accB, o);
    }
    int wid = tid >> 5, lane = tid & 31;
    if (lane == 0) { rN[wid] = accN; rD[wid] = accD; rB[wid] = accB; }
    __syncthreads();
    if (tid == 0) {
        float n = 0.0f, d = 0.0f, b = 0.0f;
#pragma unroll
        for (int i = 0; i < 8; i++) { n += rN[i]; d += rD[i]; b += rB[i]; }
        atomicAdd(&g_acc[0], (double)n);
        atomicAdd(&g_acc[1], (double)d);
        atomicAdd(&g_acc[2], (double)b);
        __threadfence();
        unsigned tk = atomicAdd(&g_ticket, 1u);
        if (tk == (unsigned)(NTX * NTY * NCHUNK - 1)) {
            __threadfence();
            double num = 2.0 * g_acc[0];
            double den = g_acc[1];
            double vol = g_acc[2] / (8.0 * (double)CX * (double)CX);
            double dice = 1.0 - (num + 1e-3) / (den + 1e-3);
            out[0] = (float)(dice + vol);
            g_acc[0] = 0.0; g_acc[1] = 0.0; g_acc[2] = 0.0;
            g_ticket = 0u;
            __threadfence();
        }
    }
}

extern "C" void kernel_launch(void* const* d_in, const int* in_sizes, int n_in,
                              void* d_out, int out_size) {
    const float* pred = (const float*)d_in[0];
    const int*   lab  = (const int*)d_in[1];
    const float* area = (const float*)d_in[2];
    (void)in_sizes; (void)n_in; (void)out_size;

    dim3 grid(NTX, NTY, NCHUNK);
    k_fused<<<grid, 256>>>(pred, lab, area, (float*)d_out);
}